// round 2
// baseline (speedup 1.0000x reference)
#include <cuda_runtime.h>
#include <cuda_bf16.h>
#include <cstdint>
#include <cstddef>

#define MDIM 8192
#define NDIM 4096
#define KDIM 4096

#define BM 128
#define BN 128
#define BK 32
#define KT (KDIM / BK)          /* 128 k-tiles */
#define STAGES 4
#define TILE_A 8192             /* 128 x 32 bf16 bytes */
#define TILE_B 8192
#define STAGE_BYTES (2 * TILE_A + TILE_B)   /* Ahi + Alo + B = 24 KB */
#define SMEM_TOTAL (STAGES * STAGE_BYTES)   /* 96 KB */

// Scratch (device globals; runtime allocation is forbidden)
__device__ __nv_bfloat16 g_W[(size_t)NDIM * KDIM];     // 32 MB exact bf16 weights
__device__ __nv_bfloat16 g_Xhi[(size_t)MDIM * KDIM];   // 64 MB
__device__ __nv_bfloat16 g_Xlo[(size_t)MDIM * KDIM];   // 64 MB

__constant__ float c_fp4[16] = {0.0f, 0.5f, 1.0f, 1.5f, 2.0f, 3.0f, 4.0f, 6.0f,
                                -0.0f, -0.5f, -1.0f, -1.5f, -2.0f, -3.0f, -4.0f, -6.0f};

// ---------------------------------------------------------------------------
// Kernel 1: dequantize packed FP4 -> bf16 (exact). 4 packed bytes -> 8 bf16.
// ---------------------------------------------------------------------------
__global__ void dequant_kernel(const int* __restrict__ wd, const int* __restrict__ ws,
                               const float* __restrict__ gsp) {
    const float gs = *gsp;
    const int TPR = KDIM / 8;
    int t = blockIdx.x * blockDim.x + threadIdx.x;
    if (t >= NDIM * TPR) return;
    int o = t / TPR;
    int tc = t - o * TPR;

    int4 p = reinterpret_cast<const int4*>(wd)[t];

    int sbyte = ws[o * (KDIM / 16) + (tc >> 1)] & 0xFF;
    int e = (sbyte >> 3) & 0xF;
    int mant = sbyte & 7;
    float sv = (e == 0) ? (float)mant * 0.001953125f
                        : __uint_as_float(((unsigned)(e + 120) << 23) | ((unsigned)mant << 20));
    if (sbyte & 0x80) sv = -sv;
    sv *= gs;

    unsigned bytes[4] = {(unsigned)p.x & 0xFFu, (unsigned)p.y & 0xFFu,
                         (unsigned)p.z & 0xFFu, (unsigned)p.w & 0xFFu};
    __nv_bfloat16 outv[8];
#pragma unroll
    for (int j = 0; j < 4; ++j) {
        outv[2 * j]     = __float2bfloat16(c_fp4[bytes[j] & 0xF] * sv);
        outv[2 * j + 1] = __float2bfloat16(c_fp4[(bytes[j] >> 4) & 0xF] * sv);
    }
    reinterpret_cast<uint4*>(g_W)[t] = *reinterpret_cast<uint4*>(outv);
}

// ---------------------------------------------------------------------------
// Kernel 2: split fp32 x -> bf16 hi + bf16 lo residual
// ---------------------------------------------------------------------------
__global__ void convert_x_kernel(const float* __restrict__ x) {
    size_t t = (size_t)blockIdx.x * blockDim.x + threadIdx.x;
    if (t >= (size_t)MDIM * KDIM / 4) return;
    float4 v = reinterpret_cast<const float4*>(x)[t];
    float vv[4] = {v.x, v.y, v.z, v.w};
    __nv_bfloat16 h[4], l[4];
#pragma unroll
    for (int j = 0; j < 4; ++j) {
        h[j] = __float2bfloat16(vv[j]);
        l[j] = __float2bfloat16(vv[j] - __bfloat162float(h[j]));
    }
    reinterpret_cast<uint2*>(g_Xhi)[t] = *reinterpret_cast<uint2*>(h);
    reinterpret_cast<uint2*>(g_Xlo)[t] = *reinterpret_cast<uint2*>(l);
}

// ---------------------------------------------------------------------------
// GEMM helpers
// ---------------------------------------------------------------------------
// SMEM tile: [128 rows][32 bf16] = row stride 64B = 4 chunks of 16B.
// Chunk swizzle c' = c ^ ((row>>1)&3) -> conflict-free ldmatrix + cp.async stores.
__device__ __forceinline__ unsigned tile_off(int row, int chunk) {
    return (unsigned)(row * 64 + ((chunk ^ ((row >> 1) & 3)) << 4));
}

__device__ __forceinline__ void cp16(unsigned sa, const __nv_bfloat16* gp) {
    unsigned long long ga = (unsigned long long)__cvta_generic_to_global((void*)gp);
    asm volatile("cp.async.cg.shared.global [%0], [%1], 16;" :: "r"(sa), "l"(ga) : "memory");
}

__device__ __forceinline__ void ldm_x4(unsigned* r, unsigned addr) {
    asm volatile("ldmatrix.sync.aligned.m8n8.x4.shared.b16 {%0,%1,%2,%3}, [%4];"
                 : "=r"(r[0]), "=r"(r[1]), "=r"(r[2]), "=r"(r[3]) : "r"(addr));
}

__device__ __forceinline__ void mma_bf16(float* c, const unsigned* a, const unsigned* b) {
    asm volatile(
        "mma.sync.aligned.m16n8k16.row.col.f32.bf16.bf16.f32 "
        "{%0,%1,%2,%3}, {%4,%5,%6,%7}, {%8,%9}, {%0,%1,%2,%3};"
        : "+f"(c[0]), "+f"(c[1]), "+f"(c[2]), "+f"(c[3])
        : "r"(a[0]), "r"(a[1]), "r"(a[2]), "r"(a[3]), "r"(b[0]), "r"(b[1]));
}

// Fill one stage: Ahi(128x32), Alo(128x32), B(128x32). 256 threads, 6 chunks each.
__device__ __forceinline__ void load_stage(unsigned st, int kb, int m_base, int n_base, int tid) {
#pragma unroll
    for (int i = 0; i < 2; ++i) {
        int ch = tid + i * 256;            // 512 chunks per tile
        int row = ch >> 2, c = ch & 3;
        const size_t gofs = (size_t)row * KDIM + kb + c * 8;
        cp16(st + tile_off(row, c),              g_Xhi + (size_t)m_base * KDIM + gofs);
        cp16(st + TILE_A + tile_off(row, c),     g_Xlo + (size_t)m_base * KDIM + gofs);
        cp16(st + 2 * TILE_A + tile_off(row, c), g_W   + (size_t)n_base * KDIM + gofs);
    }
}

// ---------------------------------------------------------------------------
// Kernel 3: bf16 mma.sync GEMM, 4-stage cp.async pipeline.
// out[m][n] = (Xhi[m]+Xlo[m]) . W[n] + bias[n], fp32 accum.
// ---------------------------------------------------------------------------
__global__ void __launch_bounds__(256, 1) gemm_kernel(const float* __restrict__ bias,
                                                      float* __restrict__ out) {
    extern __shared__ char smem[];
    unsigned sbase;
    asm("{\n\t.reg .u64 t;\n\tcvta.to.shared.u64 t, %1;\n\tcvt.u32.u64 %0, t;\n\t}"
        : "=r"(sbase) : "l"(smem));

    const int tid  = threadIdx.x;
    const int wid  = tid >> 5;
    const int lane = tid & 31;
    const int wm = wid & 3;          // 4 warps along M
    const int wn = wid >> 2;         // 2 warps along N
    const int m_base = (int)(blockIdx.x >> 5) * BM;   // n-fastest raster
    const int n_base = (int)(blockIdx.x & 31) * BN;

    const int lgrp = lane >> 3;      // ldmatrix address group 0..3
    const int lrow = lane & 7;

    float acc[2][8][4];
#pragma unroll
    for (int i = 0; i < 2; ++i)
#pragma unroll
        for (int j = 0; j < 8; ++j)
#pragma unroll
            for (int k = 0; k < 4; ++k) acc[i][j][k] = 0.0f;

    // Prologue: stages 0..2
#pragma unroll
    for (int s = 0; s < STAGES - 1; ++s) {
        load_stage(sbase + s * STAGE_BYTES, s * BK, m_base, n_base, tid);
        asm volatile("cp.async.commit_group;" ::: "memory");
    }

    for (int kt = 0; kt < KT; ++kt) {
        asm volatile("cp.async.wait_group %0;" :: "n"(STAGES - 2) : "memory");
        __syncthreads();

        // Issue next-stage loads (buffer was fully consumed at iter kt-1)
        if (kt + STAGES - 1 < KT)
            load_stage(sbase + ((kt + STAGES - 1) % STAGES) * STAGE_BYTES,
                       (kt + STAGES - 1) * BK, m_base, n_base, tid);
        asm volatile("cp.async.commit_group;" ::: "memory");

        const unsigned st = sbase + (kt % STAGES) * STAGE_BYTES;
#pragma unroll
        for (int ks = 0; ks < 2; ++ks) {   // two k16 steps per BK=32
            unsigned ah[2][4], al[2][4], bf[4][4];
            // A fragments: m16 tiles at wm*32 + {0,16}
#pragma unroll
            for (int mt = 0; mt < 2; ++mt) {
                int row = wm * 32 + mt * 16 + lrow + (lgrp & 1) * 8;
                int ch  = 2 * ks + (lgrp >> 1);
                ldm_x4(ah[mt], st + tile_off(row, ch));
                ldm_x4(al[mt], st + TILE_A + tile_off(row, ch));
            }
            // B fragments: 8 n8-tiles, loaded as 4 x4 pairs
#pragma unroll
            for (int np = 0; np < 4; ++np) {
                int row = wn * 64 + np * 16 + lrow + (lgrp >> 1) * 8;
                int ch  = 2 * ks + (lgrp & 1);
                ldm_x4(bf[np], st + 2 * TILE_A + tile_off(row, ch));
            }
#pragma unroll
            for (int mt = 0; mt < 2; ++mt)
#pragma unroll
                for (int nt = 0; nt < 8; ++nt) {
                    mma_bf16(acc[mt][nt], ah[mt], &bf[nt >> 1][(nt & 1) * 2]);
                    mma_bf16(acc[mt][nt], al[mt], &bf[nt >> 1][(nt & 1) * 2]);
                }
        }
    }

    // Epilogue: add bias, store fp32 (float2 per acc pair)
#pragma unroll
    for (int mt = 0; mt < 2; ++mt) {
        int row0 = m_base + wm * 32 + mt * 16 + (lane >> 2);
#pragma unroll
        for (int nt = 0; nt < 8; ++nt) {
            int n0 = n_base + wn * 64 + nt * 8 + 2 * (lane & 3);
            float b0 = __ldg(bias + n0), b1 = __ldg(bias + n0 + 1);
            float2 v0 = make_float2(acc[mt][nt][0] + b0, acc[mt][nt][1] + b1);
            float2 v1 = make_float2(acc[mt][nt][2] + b0, acc[mt][nt][3] + b1);
            *reinterpret_cast<float2*>(out + (size_t)row0 * NDIM + n0) = v0;
            *reinterpret_cast<float2*>(out + (size_t)(row0 + 8) * NDIM + n0) = v1;
        }
    }
}

// ---------------------------------------------------------------------------
// Launch
// ---------------------------------------------------------------------------
extern "C" void kernel_launch(void* const* d_in, const int* in_sizes, int n_in,
                              void* d_out, int out_size) {
    (void)in_sizes; (void)n_in; (void)out_size;
    const float* x      = (const float*)d_in[0];
    const int*   wd     = (const int*)d_in[1];
    const int*   ws     = (const int*)d_in[2];
    const float* gscale = (const float*)d_in[3];
    const float* bias   = (const float*)d_in[4];
    float* out = (float*)d_out;

    dequant_kernel<<<(NDIM * (KDIM / 8) + 255) / 256, 256>>>(wd, ws, gscale);
    convert_x_kernel<<<(int)(((size_t)MDIM * KDIM / 4 + 255) / 256), 256>>>(x);

    cudaFuncSetAttribute(gemm_kernel, cudaFuncAttributeMaxDynamicSharedMemorySize, SMEM_TOTAL);
    gemm_kernel<<<(MDIM / BM) * (NDIM / BN), 256, SMEM_TOTAL>>>(bias, out);
}

// round 3
// speedup vs baseline: 1.7827x; 1.7827x over previous
#include <cuda_runtime.h>
#include <cuda_fp16.h>
#include <cstdint>
#include <cstddef>

#define MDIM 8192
#define NDIM 4096
#define KDIM 4096

#define BM 128
#define BN 128
#define BK 64
#define KT (KDIM / BK)          /* 64 k-tiles */
#define STAGES 4
#define TILE_BYTES 16384        /* 128 x 64 fp16 */
#define STAGE_BYTES (2 * TILE_BYTES)        /* A + B = 32 KB */
#define SMEM_TOTAL (STAGES * STAGE_BYTES)   /* 128 KB */

// Scratch (device globals; runtime allocation forbidden)
__device__ __half g_W[(size_t)NDIM * KDIM];    // 32 MB, exact fp16 weights
__device__ __half g_X[(size_t)MDIM * KDIM];    // 64 MB, fp16 x

__constant__ float c_fp4[16] = {0.0f, 0.5f, 1.0f, 1.5f, 2.0f, 3.0f, 4.0f, 6.0f,
                                -0.0f, -0.5f, -1.0f, -1.5f, -2.0f, -3.0f, -4.0f, -6.0f};

// ---------------------------------------------------------------------------
// Kernel 1: dequantize packed FP4 -> fp16 (exact). 4 packed bytes -> 8 fp16.
// ---------------------------------------------------------------------------
__global__ void dequant_kernel(const int* __restrict__ wd, const int* __restrict__ ws,
                               const float* __restrict__ gsp) {
    const float gs = *gsp;
    const int TPR = KDIM / 8;
    int t = blockIdx.x * blockDim.x + threadIdx.x;
    if (t >= NDIM * TPR) return;
    int o = t / TPR;
    int tc = t - o * TPR;

    int4 p = reinterpret_cast<const int4*>(wd)[t];

    int sbyte = ws[o * (KDIM / 16) + (tc >> 1)] & 0xFF;
    int e = (sbyte >> 3) & 0xF;
    int mant = sbyte & 7;
    float sv = (e == 0) ? (float)mant * 0.001953125f
                        : __uint_as_float(((unsigned)(e + 120) << 23) | ((unsigned)mant << 20));
    if (sbyte & 0x80) sv = -sv;
    sv *= gs;

    unsigned bytes[4] = {(unsigned)p.x & 0xFFu, (unsigned)p.y & 0xFFu,
                         (unsigned)p.z & 0xFFu, (unsigned)p.w & 0xFFu};
    __half outv[8];
#pragma unroll
    for (int j = 0; j < 4; ++j) {
        outv[2 * j]     = __float2half_rn(c_fp4[bytes[j] & 0xF] * sv);
        outv[2 * j + 1] = __float2half_rn(c_fp4[(bytes[j] >> 4) & 0xF] * sv);
    }
    reinterpret_cast<uint4*>(g_W)[t] = *reinterpret_cast<uint4*>(outv);
}

// ---------------------------------------------------------------------------
// Kernel 2: convert fp32 x -> fp16
// ---------------------------------------------------------------------------
__global__ void convert_x_kernel(const float* __restrict__ x) {
    size_t t = (size_t)blockIdx.x * blockDim.x + threadIdx.x;
    if (t >= (size_t)MDIM * KDIM / 8) return;
    float4 v0 = reinterpret_cast<const float4*>(x)[2 * t];
    float4 v1 = reinterpret_cast<const float4*>(x)[2 * t + 1];
    __half h[8];
    h[0] = __float2half_rn(v0.x); h[1] = __float2half_rn(v0.y);
    h[2] = __float2half_rn(v0.z); h[3] = __float2half_rn(v0.w);
    h[4] = __float2half_rn(v1.x); h[5] = __float2half_rn(v1.y);
    h[6] = __float2half_rn(v1.z); h[7] = __float2half_rn(v1.w);
    reinterpret_cast<uint4*>(g_X)[t] = *reinterpret_cast<uint4*>(h);
}

// ---------------------------------------------------------------------------
// GEMM helpers
// ---------------------------------------------------------------------------
// SMEM tile: [128 rows][64 fp16] = 128B row stride, 8 chunks of 16B.
// Swizzle: chunk' = chunk ^ (row & 7) -> conflict-free ldmatrix + stores.
__device__ __forceinline__ unsigned tile_off(int row, int chunk) {
    return (unsigned)(row * 128 + ((chunk ^ (row & 7)) << 4));
}

__device__ __forceinline__ void cp16(unsigned sa, const __half* gp) {
    unsigned long long ga = (unsigned long long)__cvta_generic_to_global((void*)gp);
    asm volatile("cp.async.cg.shared.global [%0], [%1], 16;" :: "r"(sa), "l"(ga) : "memory");
}

__device__ __forceinline__ void ldm_x4(unsigned* r, unsigned addr) {
    asm volatile("ldmatrix.sync.aligned.m8n8.x4.shared.b16 {%0,%1,%2,%3}, [%4];"
                 : "=r"(r[0]), "=r"(r[1]), "=r"(r[2]), "=r"(r[3]) : "r"(addr));
}

__device__ __forceinline__ void mma_f16(float* c, const unsigned* a, const unsigned* b) {
    asm volatile(
        "mma.sync.aligned.m16n8k16.row.col.f32.f16.f16.f32 "
        "{%0,%1,%2,%3}, {%4,%5,%6,%7}, {%8,%9}, {%0,%1,%2,%3};"
        : "+f"(c[0]), "+f"(c[1]), "+f"(c[2]), "+f"(c[3])
        : "r"(a[0]), "r"(a[1]), "r"(a[2]), "r"(a[3]), "r"(b[0]), "r"(b[1]));
}

// Fill one stage: A(128x64), B(128x64). 256 threads x 8 chunks.
__device__ __forceinline__ void load_stage(unsigned st, int kb, int m_base, int n_base, int tid) {
#pragma unroll
    for (int i = 0; i < 4; ++i) {
        int ch = tid + i * 256;            // 1024 chunks per tile
        int row = ch >> 3, c = ch & 7;
        const size_t gofs = (size_t)row * KDIM + kb + c * 8;
        cp16(st + tile_off(row, c),              g_X + (size_t)m_base * KDIM + gofs);
        cp16(st + TILE_BYTES + tile_off(row, c), g_W + (size_t)n_base * KDIM + gofs);
    }
}

// ---------------------------------------------------------------------------
// Kernel 3: fp16 mma.sync GEMM, 4-stage cp.async pipeline.
// out[m][n] = X[m] . W[n] + bias[n], fp32 accum.
// ---------------------------------------------------------------------------
__global__ void __launch_bounds__(256, 1) gemm_kernel(const float* __restrict__ bias,
                                                      float* __restrict__ out) {
    extern __shared__ char smem[];
    unsigned sbase;
    asm("{\n\t.reg .u64 t;\n\tcvta.to.shared.u64 t, %1;\n\tcvt.u32.u64 %0, t;\n\t}"
        : "=r"(sbase) : "l"(smem));

    const int tid  = threadIdx.x;
    const int wid  = tid >> 5;
    const int lane = tid & 31;
    const int wm = wid & 3;          // 4 warps along M (32 rows each)
    const int wn = wid >> 2;         // 2 warps along N (64 cols each)
    const int m_base = (int)(blockIdx.x >> 5) * BM;   // n-fastest raster
    const int n_base = (int)(blockIdx.x & 31) * BN;

    const int lgrp = lane >> 3;
    const int lrow = lane & 7;

    float acc[2][8][4];
#pragma unroll
    for (int i = 0; i < 2; ++i)
#pragma unroll
        for (int j = 0; j < 8; ++j)
#pragma unroll
            for (int k = 0; k < 4; ++k) acc[i][j][k] = 0.0f;

#pragma unroll
    for (int s = 0; s < STAGES - 1; ++s) {
        load_stage(sbase + s * STAGE_BYTES, s * BK, m_base, n_base, tid);
        asm volatile("cp.async.commit_group;" ::: "memory");
    }

    for (int kt = 0; kt < KT; ++kt) {
        asm volatile("cp.async.wait_group %0;" :: "n"(STAGES - 2) : "memory");
        __syncthreads();

        if (kt + STAGES - 1 < KT)
            load_stage(sbase + ((kt + STAGES - 1) % STAGES) * STAGE_BYTES,
                       (kt + STAGES - 1) * BK, m_base, n_base, tid);
        asm volatile("cp.async.commit_group;" ::: "memory");

        const unsigned st = sbase + (kt % STAGES) * STAGE_BYTES;
#pragma unroll
        for (int ks = 0; ks < 4; ++ks) {   // four k16 steps per BK=64
            unsigned af[2][4], bf[4][4];
#pragma unroll
            for (int mt = 0; mt < 2; ++mt) {
                int row = wm * 32 + mt * 16 + lrow + (lgrp & 1) * 8;
                int ch  = 2 * ks + (lgrp >> 1);
                ldm_x4(af[mt], st + tile_off(row, ch));
            }
#pragma unroll
            for (int np = 0; np < 4; ++np) {
                int row = wn * 64 + np * 16 + lrow + (lgrp >> 1) * 8;
                int ch  = 2 * ks + (lgrp & 1);
                ldm_x4(bf[np], st + TILE_BYTES + tile_off(row, ch));
            }
#pragma unroll
            for (int mt = 0; mt < 2; ++mt)
#pragma unroll
                for (int nt = 0; nt < 8; ++nt)
                    mma_f16(acc[mt][nt], af[mt], &bf[nt >> 1][(nt & 1) * 2]);
        }
    }

    // Epilogue: add bias, store fp32
#pragma unroll
    for (int mt = 0; mt < 2; ++mt) {
        int row0 = m_base + wm * 32 + mt * 16 + (lane >> 2);
#pragma unroll
        for (int nt = 0; nt < 8; ++nt) {
            int n0 = n_base + wn * 64 + nt * 8 + 2 * (lane & 3);
            float b0 = __ldg(bias + n0), b1 = __ldg(bias + n0 + 1);
            float2 v0 = make_float2(acc[mt][nt][0] + b0, acc[mt][nt][1] + b1);
            float2 v1 = make_float2(acc[mt][nt][2] + b0, acc[mt][nt][3] + b1);
            *reinterpret_cast<float2*>(out + (size_t)row0 * NDIM + n0) = v0;
            *reinterpret_cast<float2*>(out + (size_t)(row0 + 8) * NDIM + n0) = v1;
        }
    }
}

// ---------------------------------------------------------------------------
// Launch
// ---------------------------------------------------------------------------
extern "C" void kernel_launch(void* const* d_in, const int* in_sizes, int n_in,
                              void* d_out, int out_size) {
    (void)in_sizes; (void)n_in; (void)out_size;
    const float* x      = (const float*)d_in[0];
    const int*   wd     = (const int*)d_in[1];
    const int*   ws     = (const int*)d_in[2];
    const float* gscale = (const float*)d_in[3];
    const float* bias   = (const float*)d_in[4];
    float* out = (float*)d_out;

    dequant_kernel<<<(NDIM * (KDIM / 8) + 255) / 256, 256>>>(wd, ws, gscale);
    convert_x_kernel<<<(int)(((size_t)MDIM * KDIM / 8 + 255) / 256), 256>>>(x);

    cudaFuncSetAttribute(gemm_kernel, cudaFuncAttributeMaxDynamicSharedMemorySize, SMEM_TOTAL);
    gemm_kernel<<<(MDIM / BM) * (NDIM / BN), 256, SMEM_TOTAL>>>(bias, out);
}